// round 4
// baseline (speedup 1.0000x reference)
#include <cuda_runtime.h>
#include <math.h>

#define NC   1000
#define NA   64
#define NBLK 32

// Scratch + arrival counter. __device__ globals (no allocation allowed).
// g_count self-resets each launch (last block zeroes it), so graph replays work.
__device__ float g_pp[1024];
__device__ int   g_count = 0;

// Single fused kernel:
//   Phase 1 (all 32 blocks): pp[row] = sum_k W[row,k]*P[row,k], warp per row.
//   Arrival: threadfence + atomicAdd; the LAST block to arrive (no spinning)
//   runs the solver with its 1024 threads; all others exit.
//   Solver: q = softmax(pp); c = argmax(p0); per-class register scan for the
//   first non-violating omega step (prefix property of the linear blend);
//   istar = max_j t_j carrying omega_star through the reduction.
__global__ __launch_bounds__(1024) void fused_kernel(const float* __restrict__ p0,
                                                     const float* __restrict__ P,
                                                     const float* __restrict__ W,
                                                     const float* __restrict__ omega,
                                                     float* __restrict__ out) {
    __shared__ int   s_last;
    __shared__ float red_a[32], red_b[32], red_c[32];
    __shared__ int   red_i[32];
    __shared__ float s_maxpp, s_sumexp, s_p0c, s_ppc, s_omstar;
    __shared__ int   s_c;

    const unsigned FULL = 0xffffffffu;
    int tid  = threadIdx.x;
    int lane = tid & 31;
    int wid  = tid >> 5;
    int gw   = blockIdx.x * 32 + wid;   // global warp id == row

    // ---------------- Phase 1: pp rows ----------------
    if (gw < NC) {
        const float2* w2 = reinterpret_cast<const float2*>(W + gw * NA);
        const float2* p2 = reinterpret_cast<const float2*>(P + gw * NA);
        float2 w = w2[lane];
        float2 p = p2[lane];
        float s = w.x * p.x + w.y * p.y;
        #pragma unroll
        for (int off = 16; off; off >>= 1)
            s += __shfl_down_sync(FULL, s, off);
        if (lane == 0) {
            g_pp[gw] = s;
            __threadfence();   // release this row's result device-wide
        }
    }
    __syncthreads();

    // ---------------- Arrival: elect the last block ----------------
    if (tid == 0) {
        __threadfence();
        int old = atomicAdd(&g_count, 1);
        int last = (old == NBLK - 1);
        s_last = last;
        if (last) g_count = 0;           // reset for next graph replay
    }
    __syncthreads();
    if (!s_last) return;                 // non-last blocks done; no spinning
    __threadfence();                     // acquire side before reading g_pp

    // ---------------- Solver (1024 threads of the last block) ----------------
    bool live = (tid < NC);
    float w0 = omega[0];
    w0 = fminf(fmaxf(w0, 0.0f), 1.0f);

    float p0v = live ? p0[tid] : -INFINITY;
    float ppv = live ? __ldcg(&g_pp[tid]) : -INFINITY;

    // Phase A: max(pp)  +  argmax(p0) carrying pp (for qc) — one sync pair.
    {
        float m  = ppv;
        float av = p0v;
        int   ai = tid;
        float aw = ppv;
        #pragma unroll
        for (int off = 16; off; off >>= 1) {
            m = fmaxf(m, __shfl_down_sync(FULL, m, off));
            float ov = __shfl_down_sync(FULL, av, off);
            int   oi = __shfl_down_sync(FULL, ai, off);
            float ow = __shfl_down_sync(FULL, aw, off);
            if (ov > av || (ov == av && oi < ai)) { av = ov; ai = oi; aw = ow; }
        }
        if (lane == 0) { red_a[wid] = m; red_b[wid] = av; red_i[wid] = ai; red_c[wid] = aw; }
        __syncthreads();
        if (wid == 0) {
            float x  = red_a[lane];
            float bv = red_b[lane];
            int   bi = red_i[lane];
            float bw = red_c[lane];
            #pragma unroll
            for (int off = 16; off; off >>= 1) {
                x = fmaxf(x, __shfl_down_sync(FULL, x, off));
                float ov = __shfl_down_sync(FULL, bv, off);
                int   oi = __shfl_down_sync(FULL, bi, off);
                float ow = __shfl_down_sync(FULL, bw, off);
                if (ov > bv || (ov == bv && oi < bi)) { bv = ov; bi = oi; bw = ow; }
            }
            if (lane == 0) { s_maxpp = x; s_c = bi; s_p0c = bv; s_ppc = bw; }
        }
        __syncthreads();
    }

    // Phase B: sum(exp(pp - max)).
    float e = live ? expf(ppv - s_maxpp) : 0.0f;
    {
        float s = e;
        #pragma unroll
        for (int off = 16; off; off >>= 1)
            s += __shfl_down_sync(FULL, s, off);
        if (lane == 0) red_a[wid] = s;
        __syncthreads();
        if (wid == 0) {
            float x = red_a[lane];
            #pragma unroll
            for (int off = 16; off; off >>= 1)
                x += __shfl_down_sync(FULL, x, off);
            if (lane == 0) s_sumexp = x;
        }
        __syncthreads();
    }
    float qv  = e / s_sumexp;
    int   c   = s_c;
    float p0c = s_p0c;
    float qc  = expf(s_ppc - s_maxpp) / s_sumexp;

    // Per-class scan: t_j = first i where j no longer beats c in argmax order
    // (j<c: vj >= vc ; j>c: vj > vc).  Exact float omega recurrence; cur ends
    // holding omega at the stop index.  Underflow caps the sequence.
    int   t   = 0;
    float cur = w0;
    if (live && tid != c) {
        int i = 0;
        while (true) {
            float onem = 1.0f - cur;
            float vc = onem * p0c + cur * qc;
            float vj = onem * p0v + cur * qv;
            bool viol = (tid < c) ? (vj >= vc) : (vj > vc);
            if (!viol) { t = i; break; }
            float dec = cur - 0.01f;
            if (dec < 0.001f) { t = i; break; }   // forced stop (underflow)
            cur = dec;
            ++i;
        }
    }

    // Phase C: istar = max(t), carrying omega_star (equal t => identical cur).
    {
        int   mt = t;
        float mo = cur;
        #pragma unroll
        for (int off = 16; off; off >>= 1) {
            int   ot = __shfl_down_sync(FULL, mt, off);
            float oo = __shfl_down_sync(FULL, mo, off);
            if (ot > mt) { mt = ot; mo = oo; }
        }
        if (lane == 0) { red_i[wid] = mt; red_a[wid] = mo; }
        __syncthreads();
        if (wid == 0) {
            int   xt = red_i[lane];
            float xo = red_a[lane];
            #pragma unroll
            for (int off = 16; off; off >>= 1) {
                int   ot = __shfl_down_sync(FULL, xt, off);
                float oo = __shfl_down_sync(FULL, xo, off);
                if (ot > xt) { xt = ot; xo = oo; }
            }
            if (lane == 0) s_omstar = xo;
        }
        __syncthreads();
    }

    // Output: p = (1-omega*) * p0 + omega* * q, shape (1, NC).
    if (live) {
        float om = s_omstar;
        out[tid] = (1.0f - om) * p0v + om * qv;
    }
}

extern "C" void kernel_launch(void* const* d_in, const int* in_sizes, int n_in,
                              void* d_out, int out_size) {
    const float* p0 = (const float*)d_in[0];
    const float* P  = (const float*)d_in[1];
    const float* W  = (const float*)d_in[2];
    const float* om = (const float*)d_in[3];
    float* out = (float*)d_out;

    fused_kernel<<<NBLK, 1024>>>(p0, P, W, om, out);
}